// round 12
// baseline (speedup 1.0000x reference)
#include <cuda_runtime.h>
#include <cuda_fp16.h>

#define NN 50000
#define EE 800000
#define FF 128
#define HH 128
#define HH2 64
#define TT 8
#define GG 64

// scratch (static device allocations are allowed)
__device__ __align__(16) float  g_dinv[NN];
__device__ __align__(16) __half g_hsh[NN * HH];   // raw x@W in fp16
__device__ __align__(16) float  g_pooled[GG * HH];
__device__ int  g_cnt[NN];        // in-degree (excl self-loop)
__device__ int  g_head[NN];       // linked-list heads (-1 = empty)
__device__ __align__(8) int2 g_link[EE];  // {src, next}

__device__ __forceinline__ void red4(float* p, float4 v) {
    asm volatile("red.global.add.v4.f32 [%0], {%1,%2,%3,%4};"
                 :: "l"(p), "f"(v.x), "f"(v.y), "f"(v.z), "f"(v.w) : "memory");
}

__device__ __forceinline__ float to_tf32(float f) {
    unsigned o;
    asm("cvt.rna.tf32.f32 %0, %1;" : "=r"(o) : "f"(f));
    return __uint_as_float(o);
}

__device__ __forceinline__ void mma_tf32(float* d, const unsigned* a, const unsigned* b) {
    asm("mma.sync.aligned.m16n8k8.row.col.f32.tf32.tf32.f32 "
        "{%0,%1,%2,%3},{%4,%5,%6,%7},{%8,%9},{%0,%1,%2,%3};"
        : "+f"(d[0]), "+f"(d[1]), "+f"(d[2]), "+f"(d[3])
        : "r"(a[0]), "r"(a[1]), "r"(a[2]), "r"(a[3]), "r"(b[0]), "r"(b[1]));
}

// -------------------------------------------------------------------------
// one pass: in-degree count + linked-list adjacency
__global__ void k_edges(const int* __restrict__ ei) {
    int e = blockIdx.x * blockDim.x + threadIdx.x;
    if (e >= EE) return;
    int src = __ldg(ei + e);
    int dst = __ldg(ei + EE + e);
    atomicAdd(&g_cnt[dst], 1);
    int old = atomicExch(&g_head[dst], e);
    g_link[e] = make_int2(src, old);      // coalesced in e
}

__global__ void k_dinv() {
    int i = blockIdx.x * blockDim.x + threadIdx.x;
    if (i < NN) g_dinv[i] = rsqrtf((float)(g_cnt[i] + 1));  // +1 self-loop
}

// -------------------------------------------------------------------------
// hs = x @ W (raw), tf32 tensor cores, stored as fp16. No dinv dependency.
#define GM 128
#define KC 32
#define XS_STRIDE 36
#define WS_STRIDE 136
__global__ __launch_bounds__(256) void k_gemm(const float* __restrict__ x,
                                              const float* __restrict__ W) {
    __shared__ float xs[GM * XS_STRIDE];
    __shared__ float ws[KC * WS_STRIDE];
    int tid = threadIdx.x;
    int wid = tid >> 5;
    int lane = tid & 31;
    int l4 = lane >> 2;
    int lm4 = lane & 3;
    int warpM = wid >> 1;
    int warpN = wid & 1;
    int row0 = blockIdx.x * GM;

    float acc[2][8][4];
#pragma unroll
    for (int i = 0; i < 2; i++)
#pragma unroll
        for (int j = 0; j < 8; j++)
#pragma unroll
            for (int q = 0; q < 4; q++) acc[i][j][q] = 0.0f;

    for (int kc = 0; kc < FF; kc += KC) {
#pragma unroll
        for (int q = 0; q < 4; q++) {
            int idx = tid + q * 256;
            int r = idx >> 3;
            int c4 = idx & 7;
            int gr = row0 + r;
            float4 v = make_float4(0.f, 0.f, 0.f, 0.f);
            if (gr < NN) v = *(const float4*)(x + (size_t)gr * FF + kc + c4 * 4);
            float* d = &xs[r * XS_STRIDE + c4 * 4];
            d[0] = to_tf32(v.x); d[1] = to_tf32(v.y);
            d[2] = to_tf32(v.z); d[3] = to_tf32(v.w);
        }
#pragma unroll
        for (int q = 0; q < 4; q++) {
            int idx = tid + q * 256;
            int r = idx >> 5;
            int c4 = idx & 31;
            float4 v = *(const float4*)(W + (size_t)(kc + r) * HH + c4 * 4);
            float* d = &ws[r * WS_STRIDE + c4 * 4];
            d[0] = to_tf32(v.x); d[1] = to_tf32(v.y);
            d[2] = to_tf32(v.z); d[3] = to_tf32(v.w);
        }
        __syncthreads();

#pragma unroll
        for (int ks = 0; ks < KC; ks += 8) {
            unsigned afr[2][4];
#pragma unroll
            for (int i = 0; i < 2; i++) {
                int rA = warpM * 32 + i * 16;
                afr[i][0] = __float_as_uint(xs[(rA + l4)     * XS_STRIDE + ks + lm4]);
                afr[i][1] = __float_as_uint(xs[(rA + l4 + 8) * XS_STRIDE + ks + lm4]);
                afr[i][2] = __float_as_uint(xs[(rA + l4)     * XS_STRIDE + ks + lm4 + 4]);
                afr[i][3] = __float_as_uint(xs[(rA + l4 + 8) * XS_STRIDE + ks + lm4 + 4]);
            }
#pragma unroll
            for (int j = 0; j < 8; j++) {
                int n0 = warpN * 64 + j * 8;
                unsigned bfr[2];
                bfr[0] = __float_as_uint(ws[(ks + lm4)     * WS_STRIDE + n0 + l4]);
                bfr[1] = __float_as_uint(ws[(ks + lm4 + 4) * WS_STRIDE + n0 + l4]);
                mma_tf32(acc[0][j], afr[0], bfr);
                mma_tf32(acc[1][j], afr[1], bfr);
            }
        }
        __syncthreads();
    }

#pragma unroll
    for (int i = 0; i < 2; i++) {
#pragma unroll
        for (int h = 0; h < 2; h++) {
            int r = row0 + warpM * 32 + i * 16 + h * 8 + l4;
            if (r < NN) {
#pragma unroll
                for (int j = 0; j < 8; j++) {
                    int col = warpN * 64 + j * 8 + 2 * lm4;
                    __half2 hv = __floats2half2_rn(acc[i][j][2 * h],
                                                   acc[i][j][2 * h + 1]);
                    *(__half2*)(g_hsh + (size_t)r * HH + col) = hv;
                }
            }
        }
    }
}

// -------------------------------------------------------------------------
// linked-list gather + fused pool.  One warp per node; 8 nodes per block.
// a = hs[w]*dinv[w] + sum_src hs[src]*dinv[src];  p = relu(a*dinv[w] + b).
// Block-uniform group -> smem reduce -> single red4 set per block.
__global__ __launch_bounds__(256) void k_gather(const int* __restrict__ batch,
                                                const float* __restrict__ b) {
    __shared__ int sg[8];
    __shared__ float sacc[8][132];   // padded stride, 16B-aligned rows
    int wid = threadIdx.x >> 5;
    int lane = threadIdx.x & 31;
    int w = blockIdx.x * 8 + wid;    // NN = 50000 = 6250*8, always valid
    size_t coff = (size_t)lane * 4;

    float dw = g_dinv[w];
    uint2 us = __ldg((const uint2*)(g_hsh + (size_t)w * HH + coff));
    float2 f0 = __half22float2(*(__half2*)&us.x);
    float2 f1 = __half22float2(*(__half2*)&us.y);
    float4 a = make_float4(f0.x * dw, f0.y * dw, f1.x * dw, f1.y * dw);

    int e = g_head[w];               // uniform across warp
    while (e >= 0) {
        int2 le = __ldg(&g_link[e]); // uniform broadcast load
        float ds = __ldg(&g_dinv[le.x]);
        uint2 u = __ldg((const uint2*)(g_hsh + (size_t)le.x * HH + coff));
        float2 p0 = __half22float2(*(__half2*)&u.x);
        float2 p1 = __half22float2(*(__half2*)&u.y);
        a.x += p0.x * ds; a.y += p0.y * ds;
        a.z += p1.x * ds; a.w += p1.y * ds;
        e = le.y;
    }

    float4 bb = *(const float4*)(b + coff);
    float4 p;
    p.x = fmaxf(a.x * dw + bb.x, 0.f);
    p.y = fmaxf(a.y * dw + bb.y, 0.f);
    p.z = fmaxf(a.z * dw + bb.z, 0.f);
    p.w = fmaxf(a.w * dw + bb.w, 0.f);

    int g = __ldg(batch + w);
    if (lane == 0) sg[wid] = g;
    __syncthreads();
    int g0 = sg[0];
    bool uni = true;
#pragma unroll
    for (int i = 1; i < 8; i++) uni &= (sg[i] == g0);

    if (uni) {
        *(float4*)&sacc[wid][lane * 4] = p;
        __syncthreads();
        if (wid == 0) {
            float4 s = make_float4(0.f, 0.f, 0.f, 0.f);
#pragma unroll
            for (int k = 0; k < 8; k++) {
                float4 v = *(const float4*)&sacc[k][lane * 4];
                s.x += v.x; s.y += v.y; s.z += v.z; s.w += v.w;
            }
            red4(g_pooled + (size_t)g0 * HH + coff, s);
        }
    } else {
        red4(g_pooled + (size_t)g * HH + coff, p);   // rare boundary blocks
    }
}

// -------------------------------------------------------------------------
__global__ __launch_bounds__(256) void k_head(const int* __restrict__ batch,
                                              const float* __restrict__ fc1_w,
                                              const float* __restrict__ fc1_b,
                                              const float* __restrict__ aw,
                                              const float* __restrict__ ab,
                                              const float* __restrict__ cw,
                                              const float* __restrict__ cb,
                                              float* __restrict__ out) {
    __shared__ float s_gs[GG * HH];
    __shared__ float s_z[GG * HH2];
    __shared__ float s_logit[GG * TT];
    __shared__ int s_lb[GG + 1];
    int tid = threadIdx.x;

    if (tid <= GG) {
        int g = tid, lo = 0, hi = NN;
        while (lo < hi) {
            int mid = (lo + hi) >> 1;
            if (batch[mid] < g) lo = mid + 1; else hi = mid;
        }
        s_lb[tid] = lo;
    }
    __syncthreads();

    for (int i = tid; i < GG * HH; i += 256) {
        int g = i >> 7;
        float c = (float)(s_lb[g + 1] - s_lb[g]);
        s_gs[i] = g_pooled[i] / fmaxf(c, 1.0f);
    }
    __syncthreads();

    for (int o = tid; o < GG * HH2; o += 256) {
        int g = o >> 6, j = o & 63;
        float s = fc1_b[j];
        const float* gr = &s_gs[g * HH];
#pragma unroll 8
        for (int k = 0; k < HH; k++) s += gr[k] * fc1_w[k * HH2 + j];
        s_z[o] = fmaxf(s, 0.f);
    }
    __syncthreads();

    for (int o = tid; o < GG * TT; o += 256) {
        int g = o >> 3, t = o & 7;
        float s = ab[t];
        const float* zr = &s_z[g * HH2];
#pragma unroll
        for (int k = 0; k < HH2; k++) s += zr[k] * aw[k * TT + t];
        s_logit[o] = s;
    }
    if (tid < GG) {
        float s = cb[0];
        const float* zr = &s_z[tid * HH2];
#pragma unroll
        for (int k = 0; k < HH2; k++) s += zr[k] * cw[k];
        out[GG * TT + tid] = s;
    }
    __syncthreads();

    if (tid < GG) {
        float m = -1e30f;
#pragma unroll
        for (int t = 0; t < TT; t++) m = fmaxf(m, s_logit[tid * TT + t]);
        float e[TT], sum = 0.f;
#pragma unroll
        for (int t = 0; t < TT; t++) { e[t] = expf(s_logit[tid * TT + t] - m); sum += e[t]; }
        float inv = 1.0f / sum;
#pragma unroll
        for (int t = 0; t < TT; t++) out[tid * TT + t] = e[t] * inv;
    }
}

// -------------------------------------------------------------------------
extern "C" void kernel_launch(void* const* d_in, const int* in_sizes, int n_in,
                              void* d_out, int out_size) {
    const float* x     = (const float*)d_in[0];
    const int*   ei    = (const int*)d_in[1];
    const int*   batch = (const int*)d_in[2];
    const float* W     = (const float*)d_in[3];
    const float* b     = (const float*)d_in[4];
    const float* fc1_w = (const float*)d_in[5];
    const float* fc1_b = (const float*)d_in[6];
    const float* aw    = (const float*)d_in[7];
    const float* ab    = (const float*)d_in[8];
    const float* cw    = (const float*)d_in[9];
    const float* cb    = (const float*)d_in[10];
    float* out = (float*)d_out;

    void *p_cnt, *p_head, *p_pooled;
    cudaGetSymbolAddress(&p_cnt,    g_cnt);
    cudaGetSymbolAddress(&p_head,   g_head);
    cudaGetSymbolAddress(&p_pooled, g_pooled);

    cudaStream_t s2;
    cudaStreamCreateWithFlags(&s2, cudaStreamNonBlocking);
    cudaEvent_t eFork, eSide;
    cudaEventCreateWithFlags(&eFork, cudaEventDisableTiming);
    cudaEventCreateWithFlags(&eSide, cudaEventDisableTiming);

    // main stream: zero pooled, fork, GEMM (no dependencies on edge data)
    cudaMemsetAsync(p_pooled, 0, GG * HH * sizeof(float), 0);
    cudaEventRecord(eFork, 0);
    cudaStreamWaitEvent(s2, eFork, 0);

    // side stream: adjacency build + dinv
    cudaMemsetAsync(p_cnt,  0x00, NN * sizeof(int), s2);
    cudaMemsetAsync(p_head, 0xFF, NN * sizeof(int), s2);   // -1
    k_edges<<<(EE + 255) / 256, 256, 0, s2>>>(ei);
    k_dinv<<<(NN + 255) / 256, 256, 0, s2>>>();
    cudaEventRecord(eSide, s2);

    k_gemm<<<(NN + GM - 1) / GM, 256>>>(x, W);

    // join: gather needs hs (main) + adjacency/dinv (side)
    cudaStreamWaitEvent(0, eSide, 0);
    k_gather<<<NN / 8, 256>>>(batch, b);
    k_head<<<1, 256>>>(batch, fc1_w, fc1_b, aw, ab, cw, cb, out);
}

// round 13
// speedup vs baseline: 1.1881x; 1.1881x over previous
#include <cuda_runtime.h>
#include <cuda_fp16.h>

#define NN 50000
#define EE 800000
#define FF 128
#define HH 128
#define HH2 64
#define TT 8
#define GG 64
#define CAP 128   // bucket capacity per node (mean deg 16, P(>128) ~ 0)

// scratch (static device allocations are allowed)
__device__ __align__(16) float  g_dinv[NN];
__device__ __align__(16) __half g_hsh[NN * HH];   // raw x@W in fp16
__device__ __align__(16) float  g_pooled[GG * HH];
__device__ int g_cnt[NN];               // in-degree (excl self-loop)
__device__ int g_bucket[NN * CAP];      // per-node incoming src lists

__device__ __forceinline__ void red4(float* p, float4 v) {
    asm volatile("red.global.add.v4.f32 [%0], {%1,%2,%3,%4};"
                 :: "l"(p), "f"(v.x), "f"(v.y), "f"(v.z), "f"(v.w) : "memory");
}

__device__ __forceinline__ float to_tf32(float f) {
    unsigned o;
    asm("cvt.rna.tf32.f32 %0, %1;" : "=r"(o) : "f"(f));
    return __uint_as_float(o);
}

__device__ __forceinline__ void mma_tf32(float* d, const unsigned* a, const unsigned* b) {
    asm("mma.sync.aligned.m16n8k8.row.col.f32.tf32.tf32.f32 "
        "{%0,%1,%2,%3},{%4,%5,%6,%7},{%8,%9},{%0,%1,%2,%3};"
        : "+f"(d[0]), "+f"(d[1]), "+f"(d[2]), "+f"(d[3])
        : "r"(a[0]), "r"(a[1]), "r"(a[2]), "r"(a[3]), "r"(b[0]), "r"(b[1]));
}

// -------------------------------------------------------------------------
// one pass: in-degree count + bucket fill (independent-iterable adjacency)
__global__ void k_edges(const int* __restrict__ ei) {
    int e = blockIdx.x * blockDim.x + threadIdx.x;
    if (e >= EE) return;
    int src = __ldg(ei + e);
    int dst = __ldg(ei + EE + e);
    int pos = atomicAdd(&g_cnt[dst], 1);
    if (pos < CAP) g_bucket[dst * CAP + pos] = src;
}

__global__ void k_dinv() {
    int i = blockIdx.x * blockDim.x + threadIdx.x;
    if (i < NN) g_dinv[i] = rsqrtf((float)(g_cnt[i] + 1));  // +1 self-loop
}

// -------------------------------------------------------------------------
// hs = x @ W (raw), tf32 tensor cores, stored as fp16. No dependencies.
#define GM 128
#define KC 32
#define XS_STRIDE 36
#define WS_STRIDE 136
__global__ __launch_bounds__(256) void k_gemm(const float* __restrict__ x,
                                              const float* __restrict__ W) {
    __shared__ float xs[GM * XS_STRIDE];
    __shared__ float ws[KC * WS_STRIDE];
    int tid = threadIdx.x;
    int wid = tid >> 5;
    int lane = tid & 31;
    int l4 = lane >> 2;
    int lm4 = lane & 3;
    int warpM = wid >> 1;
    int warpN = wid & 1;
    int row0 = blockIdx.x * GM;

    float acc[2][8][4];
#pragma unroll
    for (int i = 0; i < 2; i++)
#pragma unroll
        for (int j = 0; j < 8; j++)
#pragma unroll
            for (int q = 0; q < 4; q++) acc[i][j][q] = 0.0f;

    for (int kc = 0; kc < FF; kc += KC) {
#pragma unroll
        for (int q = 0; q < 4; q++) {
            int idx = tid + q * 256;
            int r = idx >> 3;
            int c4 = idx & 7;
            int gr = row0 + r;
            float4 v = make_float4(0.f, 0.f, 0.f, 0.f);
            if (gr < NN) v = *(const float4*)(x + (size_t)gr * FF + kc + c4 * 4);
            float* d = &xs[r * XS_STRIDE + c4 * 4];
            d[0] = to_tf32(v.x); d[1] = to_tf32(v.y);
            d[2] = to_tf32(v.z); d[3] = to_tf32(v.w);
        }
#pragma unroll
        for (int q = 0; q < 4; q++) {
            int idx = tid + q * 256;
            int r = idx >> 5;
            int c4 = idx & 31;
            float4 v = *(const float4*)(W + (size_t)(kc + r) * HH + c4 * 4);
            float* d = &ws[r * WS_STRIDE + c4 * 4];
            d[0] = to_tf32(v.x); d[1] = to_tf32(v.y);
            d[2] = to_tf32(v.z); d[3] = to_tf32(v.w);
        }
        __syncthreads();

#pragma unroll
        for (int ks = 0; ks < KC; ks += 8) {
            unsigned afr[2][4];
#pragma unroll
            for (int i = 0; i < 2; i++) {
                int rA = warpM * 32 + i * 16;
                afr[i][0] = __float_as_uint(xs[(rA + l4)     * XS_STRIDE + ks + lm4]);
                afr[i][1] = __float_as_uint(xs[(rA + l4 + 8) * XS_STRIDE + ks + lm4]);
                afr[i][2] = __float_as_uint(xs[(rA + l4)     * XS_STRIDE + ks + lm4 + 4]);
                afr[i][3] = __float_as_uint(xs[(rA + l4 + 8) * XS_STRIDE + ks + lm4 + 4]);
            }
#pragma unroll
            for (int j = 0; j < 8; j++) {
                int n0 = warpN * 64 + j * 8;
                unsigned bfr[2];
                bfr[0] = __float_as_uint(ws[(ks + lm4)     * WS_STRIDE + n0 + l4]);
                bfr[1] = __float_as_uint(ws[(ks + lm4 + 4) * WS_STRIDE + n0 + l4]);
                mma_tf32(acc[0][j], afr[0], bfr);
                mma_tf32(acc[1][j], afr[1], bfr);
            }
        }
        __syncthreads();
    }

#pragma unroll
    for (int i = 0; i < 2; i++) {
#pragma unroll
        for (int h = 0; h < 2; h++) {
            int r = row0 + warpM * 32 + i * 16 + h * 8 + l4;
            if (r < NN) {
#pragma unroll
                for (int j = 0; j < 8; j++) {
                    int col = warpN * 64 + j * 8 + 2 * lm4;
                    __half2 hv = __floats2half2_rn(acc[i][j][2 * h],
                                                   acc[i][j][2 * h + 1]);
                    *(__half2*)(g_hsh + (size_t)r * HH + col) = hv;
                }
            }
        }
    }
}

// -------------------------------------------------------------------------
// bucket gather + fused pool. One warp per node; 8 nodes per block.
// a = hs[w]*dinv[w] + sum_src hs[src]*dinv[src];  p = relu(a*dinv[w] + b).
// 4-way unrolled independent loads (MLP=4). Block-uniform group -> smem
// reduce -> one red4 set per block.
__global__ __launch_bounds__(256) void k_gather(const int* __restrict__ batch,
                                                const float* __restrict__ b) {
    __shared__ int sg[8];
    __shared__ float sacc[8][132];
    int wid = threadIdx.x >> 5;
    int lane = threadIdx.x & 31;
    int w = blockIdx.x * 8 + wid;    // NN = 50000 = 6250*8, always valid
    size_t coff = (size_t)lane * 4;

    float dw = g_dinv[w];
    uint2 us = __ldg((const uint2*)(g_hsh + (size_t)w * HH + coff));
    float2 f0 = __half22float2(*(__half2*)&us.x);
    float2 f1 = __half22float2(*(__half2*)&us.y);
    float4 a0 = make_float4(f0.x * dw, f0.y * dw, f1.x * dw, f1.y * dw);
    float4 a1 = make_float4(0.f, 0.f, 0.f, 0.f);

    int deg = g_cnt[w];
    if (deg > CAP) deg = CAP;
    const int* bkt = g_bucket + (size_t)w * CAP;
    int e = 0;
    for (; e + 4 <= deg; e += 4) {
        int s0 = __ldg(bkt + e);
        int s1 = __ldg(bkt + e + 1);
        int s2 = __ldg(bkt + e + 2);
        int s3 = __ldg(bkt + e + 3);
        float d0 = __ldg(&g_dinv[s0]);
        float d1 = __ldg(&g_dinv[s1]);
        float d2 = __ldg(&g_dinv[s2]);
        float d3 = __ldg(&g_dinv[s3]);
        uint2 u0 = __ldg((const uint2*)(g_hsh + (size_t)s0 * HH + coff));
        uint2 u1 = __ldg((const uint2*)(g_hsh + (size_t)s1 * HH + coff));
        uint2 u2 = __ldg((const uint2*)(g_hsh + (size_t)s2 * HH + coff));
        uint2 u3 = __ldg((const uint2*)(g_hsh + (size_t)s3 * HH + coff));
        float2 p0 = __half22float2(*(__half2*)&u0.x);
        float2 p1 = __half22float2(*(__half2*)&u0.y);
        float2 q0 = __half22float2(*(__half2*)&u1.x);
        float2 q1 = __half22float2(*(__half2*)&u1.y);
        float2 r0 = __half22float2(*(__half2*)&u2.x);
        float2 r1 = __half22float2(*(__half2*)&u2.y);
        float2 t0 = __half22float2(*(__half2*)&u3.x);
        float2 t1 = __half22float2(*(__half2*)&u3.y);
        a0.x += p0.x * d0; a0.y += p0.y * d0; a0.z += p1.x * d0; a0.w += p1.y * d0;
        a1.x += q0.x * d1; a1.y += q0.y * d1; a1.z += q1.x * d1; a1.w += q1.y * d1;
        a0.x += r0.x * d2; a0.y += r0.y * d2; a0.z += r1.x * d2; a0.w += r1.y * d2;
        a1.x += t0.x * d3; a1.y += t0.y * d3; a1.z += t1.x * d3; a1.w += t1.y * d3;
    }
    for (; e < deg; e++) {
        int s0 = __ldg(bkt + e);
        float d0 = __ldg(&g_dinv[s0]);
        uint2 u0 = __ldg((const uint2*)(g_hsh + (size_t)s0 * HH + coff));
        float2 p0 = __half22float2(*(__half2*)&u0.x);
        float2 p1 = __half22float2(*(__half2*)&u0.y);
        a0.x += p0.x * d0; a0.y += p0.y * d0; a0.z += p1.x * d0; a0.w += p1.y * d0;
    }

    float4 bb = *(const float4*)(b + coff);
    float4 p;
    p.x = fmaxf((a0.x + a1.x) * dw + bb.x, 0.f);
    p.y = fmaxf((a0.y + a1.y) * dw + bb.y, 0.f);
    p.z = fmaxf((a0.z + a1.z) * dw + bb.z, 0.f);
    p.w = fmaxf((a0.w + a1.w) * dw + bb.w, 0.f);

    int g = __ldg(batch + w);
    if (lane == 0) sg[wid] = g;
    __syncthreads();
    int g0 = sg[0];
    bool uni = true;
#pragma unroll
    for (int i = 1; i < 8; i++) uni &= (sg[i] == g0);

    if (uni) {
        *(float4*)&sacc[wid][lane * 4] = p;
        __syncthreads();
        if (wid == 0) {
            float4 s = make_float4(0.f, 0.f, 0.f, 0.f);
#pragma unroll
            for (int k = 0; k < 8; k++) {
                float4 v = *(const float4*)&sacc[k][lane * 4];
                s.x += v.x; s.y += v.y; s.z += v.z; s.w += v.w;
            }
            red4(g_pooled + (size_t)g0 * HH + coff, s);
        }
    } else {
        red4(g_pooled + (size_t)g * HH + coff, p);   // rare boundary blocks
    }
}

// -------------------------------------------------------------------------
__global__ __launch_bounds__(256) void k_head(const int* __restrict__ batch,
                                              const float* __restrict__ fc1_w,
                                              const float* __restrict__ fc1_b,
                                              const float* __restrict__ aw,
                                              const float* __restrict__ ab,
                                              const float* __restrict__ cw,
                                              const float* __restrict__ cb,
                                              float* __restrict__ out) {
    __shared__ float s_gs[GG * HH];
    __shared__ float s_z[GG * HH2];
    __shared__ float s_logit[GG * TT];
    __shared__ int s_lb[GG + 1];
    int tid = threadIdx.x;

    if (tid <= GG) {
        int g = tid, lo = 0, hi = NN;
        while (lo < hi) {
            int mid = (lo + hi) >> 1;
            if (batch[mid] < g) lo = mid + 1; else hi = mid;
        }
        s_lb[tid] = lo;
    }
    __syncthreads();

    for (int i = tid; i < GG * HH; i += 256) {
        int g = i >> 7;
        float c = (float)(s_lb[g + 1] - s_lb[g]);
        s_gs[i] = g_pooled[i] / fmaxf(c, 1.0f);
    }
    __syncthreads();

    for (int o = tid; o < GG * HH2; o += 256) {
        int g = o >> 6, j = o & 63;
        float s = fc1_b[j];
        const float* gr = &s_gs[g * HH];
#pragma unroll 8
        for (int k = 0; k < HH; k++) s += gr[k] * fc1_w[k * HH2 + j];
        s_z[o] = fmaxf(s, 0.f);
    }
    __syncthreads();

    for (int o = tid; o < GG * TT; o += 256) {
        int g = o >> 3, t = o & 7;
        float s = ab[t];
        const float* zr = &s_z[g * HH2];
#pragma unroll
        for (int k = 0; k < HH2; k++) s += zr[k] * aw[k * TT + t];
        s_logit[o] = s;
    }
    if (tid < GG) {
        float s = cb[0];
        const float* zr = &s_z[tid * HH2];
#pragma unroll
        for (int k = 0; k < HH2; k++) s += zr[k] * cw[k];
        out[GG * TT + tid] = s;
    }
    __syncthreads();

    if (tid < GG) {
        float m = -1e30f;
#pragma unroll
        for (int t = 0; t < TT; t++) m = fmaxf(m, s_logit[tid * TT + t]);
        float e[TT], sum = 0.f;
#pragma unroll
        for (int t = 0; t < TT; t++) { e[t] = expf(s_logit[tid * TT + t] - m); sum += e[t]; }
        float inv = 1.0f / sum;
#pragma unroll
        for (int t = 0; t < TT; t++) out[tid * TT + t] = e[t] * inv;
    }
}

// -------------------------------------------------------------------------
extern "C" void kernel_launch(void* const* d_in, const int* in_sizes, int n_in,
                              void* d_out, int out_size) {
    const float* x     = (const float*)d_in[0];
    const int*   ei    = (const int*)d_in[1];
    const int*   batch = (const int*)d_in[2];
    const float* W     = (const float*)d_in[3];
    const float* b     = (const float*)d_in[4];
    const float* fc1_w = (const float*)d_in[5];
    const float* fc1_b = (const float*)d_in[6];
    const float* aw    = (const float*)d_in[7];
    const float* ab    = (const float*)d_in[8];
    const float* cw    = (const float*)d_in[9];
    const float* cb    = (const float*)d_in[10];
    float* out = (float*)d_out;

    void *p_cnt, *p_pooled;
    cudaGetSymbolAddress(&p_cnt,    g_cnt);
    cudaGetSymbolAddress(&p_pooled, g_pooled);

    cudaStream_t s2;
    cudaStreamCreateWithFlags(&s2, cudaStreamNonBlocking);
    cudaEvent_t eFork, eSide;
    cudaEventCreateWithFlags(&eFork, cudaEventDisableTiming);
    cudaEventCreateWithFlags(&eSide, cudaEventDisableTiming);

    // main stream: zero pooled, fork, GEMM (no dependencies on edge data)
    cudaMemsetAsync(p_pooled, 0, GG * HH * sizeof(float), 0);
    cudaEventRecord(eFork, 0);
    cudaStreamWaitEvent(s2, eFork, 0);

    // side stream: adjacency build + dinv
    cudaMemsetAsync(p_cnt, 0x00, NN * sizeof(int), s2);
    k_edges<<<(EE + 255) / 256, 256, 0, s2>>>(ei);
    k_dinv<<<(NN + 255) / 256, 256, 0, s2>>>();
    cudaEventRecord(eSide, s2);

    k_gemm<<<(NN + GM - 1) / GM, 256>>>(x, W);

    // join: gather needs hs (main) + adjacency/dinv (side)
    cudaStreamWaitEvent(0, eSide, 0);
    k_gather<<<NN / 8, 256>>>(batch, b);
    k_head<<<1, 256>>>(batch, fc1_w, fc1_b, aw, ab, cw, cb, out);
}

// round 17
// speedup vs baseline: 1.7108x; 1.4399x over previous
#include <cuda_runtime.h>
#include <cuda_fp16.h>

#define NN 50000
#define EE 800000
#define FF 128
#define HH 128
#define HH2 64
#define TT 8
#define GG 64
#define CAP 128   // bucket capacity per node (mean deg 16, P(>128) ~ 0)

// scratch (static device allocations are allowed)
__device__ __align__(16) float  g_dinv[NN];
__device__ __align__(16) __half g_hsh[NN * HH];   // x@W, then scaled by dinv
__device__ __align__(16) float  g_pooled[GG * HH];
__device__ int g_cnt[NN];               // in-degree (excl self-loop)
__device__ __align__(16) int g_bucket[NN * CAP];  // per-node incoming src lists

__device__ __forceinline__ void red4(float* p, float4 v) {
    asm volatile("red.global.add.v4.f32 [%0], {%1,%2,%3,%4};"
                 :: "l"(p), "f"(v.x), "f"(v.y), "f"(v.z), "f"(v.w) : "memory");
}

__device__ __forceinline__ float to_tf32(float f) {
    unsigned o;
    asm("cvt.rna.tf32.f32 %0, %1;" : "=r"(o) : "f"(f));
    return __uint_as_float(o);
}

__device__ __forceinline__ void mma_tf32(float* d, const unsigned* a, const unsigned* b) {
    asm("mma.sync.aligned.m16n8k8.row.col.f32.tf32.tf32.f32 "
        "{%0,%1,%2,%3},{%4,%5,%6,%7},{%8,%9},{%0,%1,%2,%3};"
        : "+f"(d[0]), "+f"(d[1]), "+f"(d[2]), "+f"(d[3])
        : "r"(a[0]), "r"(a[1]), "r"(a[2]), "r"(a[3]), "r"(b[0]), "r"(b[1]));
}

// -------------------------------------------------------------------------
// one pass: in-degree count + bucket fill
__global__ void k_edges(const int* __restrict__ ei) {
    int e = blockIdx.x * blockDim.x + threadIdx.x;
    if (e >= EE) return;
    int src = __ldg(ei + e);
    int dst = __ldg(ei + EE + e);
    int pos = atomicAdd(&g_cnt[dst], 1);
    if (pos < CAP) g_bucket[dst * CAP + pos] = src;
}

__global__ void k_dinv() {
    int i = blockIdx.x * blockDim.x + threadIdx.x;
    if (i < NN) g_dinv[i] = rsqrtf((float)(g_cnt[i] + 1));  // +1 self-loop
}

// in-place: hsh[row] *= dinv[row]  (fp32 math, fp16 store). 16 thr/row.
__global__ __launch_bounds__(256) void k_scale() {
    int t = blockIdx.x * blockDim.x + threadIdx.x;
    if (t >= NN * 16) return;
    float d = g_dinv[t >> 4];
    uint4* p = (uint4*)(g_hsh + (size_t)t * 8);
    uint4 v = *p;
    __half2* h = (__half2*)&v;
#pragma unroll
    for (int i = 0; i < 4; i++) {
        float2 f = __half22float2(h[i]);
        h[i] = __floats2half2_rn(f.x * d, f.y * d);
    }
    *p = v;
}

// -------------------------------------------------------------------------
// hs = x @ W (raw), tf32 tensor cores, stored as fp16. No dependencies.
#define GM 128
#define KC 32
#define XS_STRIDE 36
#define WS_STRIDE 136
__global__ __launch_bounds__(256) void k_gemm(const float* __restrict__ x,
                                              const float* __restrict__ W) {
    __shared__ float xs[GM * XS_STRIDE];
    __shared__ float ws[KC * WS_STRIDE];
    int tid = threadIdx.x;
    int wid = tid >> 5;
    int lane = tid & 31;
    int l4 = lane >> 2;
    int lm4 = lane & 3;
    int warpM = wid >> 1;
    int warpN = wid & 1;
    int row0 = blockIdx.x * GM;

    float acc[2][8][4];
#pragma unroll
    for (int i = 0; i < 2; i++)
#pragma unroll
        for (int j = 0; j < 8; j++)
#pragma unroll
            for (int q = 0; q < 4; q++) acc[i][j][q] = 0.0f;

    for (int kc = 0; kc < FF; kc += KC) {
#pragma unroll
        for (int q = 0; q < 4; q++) {
            int idx = tid + q * 256;
            int r = idx >> 3;
            int c4 = idx & 7;
            int gr = row0 + r;
            float4 v = make_float4(0.f, 0.f, 0.f, 0.f);
            if (gr < NN) v = *(const float4*)(x + (size_t)gr * FF + kc + c4 * 4);
            float* d = &xs[r * XS_STRIDE + c4 * 4];
            d[0] = to_tf32(v.x); d[1] = to_tf32(v.y);
            d[2] = to_tf32(v.z); d[3] = to_tf32(v.w);
        }
#pragma unroll
        for (int q = 0; q < 4; q++) {
            int idx = tid + q * 256;
            int r = idx >> 5;
            int c4 = idx & 31;
            float4 v = *(const float4*)(W + (size_t)(kc + r) * HH + c4 * 4);
            float* d = &ws[r * WS_STRIDE + c4 * 4];
            d[0] = to_tf32(v.x); d[1] = to_tf32(v.y);
            d[2] = to_tf32(v.z); d[3] = to_tf32(v.w);
        }
        __syncthreads();

#pragma unroll
        for (int ks = 0; ks < KC; ks += 8) {
            unsigned afr[2][4];
#pragma unroll
            for (int i = 0; i < 2; i++) {
                int rA = warpM * 32 + i * 16;
                afr[i][0] = __float_as_uint(xs[(rA + l4)     * XS_STRIDE + ks + lm4]);
                afr[i][1] = __float_as_uint(xs[(rA + l4 + 8) * XS_STRIDE + ks + lm4]);
                afr[i][2] = __float_as_uint(xs[(rA + l4)     * XS_STRIDE + ks + lm4 + 4]);
                afr[i][3] = __float_as_uint(xs[(rA + l4 + 8) * XS_STRIDE + ks + lm4 + 4]);
            }
#pragma unroll
            for (int j = 0; j < 8; j++) {
                int n0 = warpN * 64 + j * 8;
                unsigned bfr[2];
                bfr[0] = __float_as_uint(ws[(ks + lm4)     * WS_STRIDE + n0 + l4]);
                bfr[1] = __float_as_uint(ws[(ks + lm4 + 4) * WS_STRIDE + n0 + l4]);
                mma_tf32(acc[0][j], afr[0], bfr);
                mma_tf32(acc[1][j], afr[1], bfr);
            }
        }
        __syncthreads();
    }

#pragma unroll
    for (int i = 0; i < 2; i++) {
#pragma unroll
        for (int h = 0; h < 2; h++) {
            int r = row0 + warpM * 32 + i * 16 + h * 8 + l4;
            if (r < NN) {
#pragma unroll
                for (int j = 0; j < 8; j++) {
                    int col = warpN * 64 + j * 8 + 2 * lm4;
                    __half2 hv = __floats2half2_rn(acc[i][j][2 * h],
                                                   acc[i][j][2 * h + 1]);
                    *(__half2*)(g_hsh + (size_t)r * HH + col) = hv;
                }
            }
        }
    }
}

// -------------------------------------------------------------------------
// bucket gather + fused pool. One warp per node; 8 nodes per block.
// hs is pre-scaled by dinv[src].  Edge loop: LDG.64 + 2 HADD2 per edge
// (fp16 accumulation, 4 independent accumulator pairs), int4-packed idx.
// p = relu((hss[w] + sum_src hss[src]) * dinv[w] + b).
__global__ __launch_bounds__(256) void k_gather(const int* __restrict__ batch,
                                                const float* __restrict__ b) {
    __shared__ int sg[8];
    __shared__ float sacc[8][132];
    int wid = threadIdx.x >> 5;
    int lane = threadIdx.x & 31;
    int w = blockIdx.x * 8 + wid;    // NN = 50000 = 6250*8, always valid
    size_t coff = (size_t)lane * 4;

    // self term (already contains one dinv[w] factor) in fp32
    uint2 us = __ldg((const uint2*)(g_hsh + (size_t)w * HH + coff));
    float2 f0 = __half22float2(*(__half2*)&us.x);
    float2 f1 = __half22float2(*(__half2*)&us.y);
    float4 a = make_float4(f0.x, f0.y, f1.x, f1.y);

    // fp16 accumulators (4 independent pairs for ILP)
    __half2 z = __float2half2_rn(0.f);
    __half2 acc0[2] = {z, z}, acc1[2] = {z, z}, acc2[2] = {z, z}, acc3[2] = {z, z};

    int deg = g_cnt[w];
    if (deg > CAP) deg = CAP;
    const int4* bkt4 = (const int4*)(g_bucket + (size_t)w * CAP);
    int q4 = deg >> 2;
    for (int i = 0; i < q4; i++) {
        int4 s = __ldg(bkt4 + i);           // uniform 16B load: 4 edges
        uint2 u0 = __ldg((const uint2*)(g_hsh + (size_t)s.x * HH + coff));
        uint2 u1 = __ldg((const uint2*)(g_hsh + (size_t)s.y * HH + coff));
        uint2 u2 = __ldg((const uint2*)(g_hsh + (size_t)s.z * HH + coff));
        uint2 u3 = __ldg((const uint2*)(g_hsh + (size_t)s.w * HH + coff));
        acc0[0] = __hadd2(acc0[0], *(__half2*)&u0.x);
        acc0[1] = __hadd2(acc0[1], *(__half2*)&u0.y);
        acc1[0] = __hadd2(acc1[0], *(__half2*)&u1.x);
        acc1[1] = __hadd2(acc1[1], *(__half2*)&u1.y);
        acc2[0] = __hadd2(acc2[0], *(__half2*)&u2.x);
        acc2[1] = __hadd2(acc2[1], *(__half2*)&u2.y);
        acc3[0] = __hadd2(acc3[0], *(__half2*)&u3.x);
        acc3[1] = __hadd2(acc3[1], *(__half2*)&u3.y);
    }
    const int* bkt = (const int*)bkt4;
    for (int e = q4 * 4; e < deg; e++) {
        int s0 = __ldg(bkt + e);
        uint2 u0 = __ldg((const uint2*)(g_hsh + (size_t)s0 * HH + coff));
        acc0[0] = __hadd2(acc0[0], *(__half2*)&u0.x);
        acc0[1] = __hadd2(acc0[1], *(__half2*)&u0.y);
    }

    // merge fp16 accumulators into fp32
    {
        float2 c00 = __half22float2(acc0[0]), c01 = __half22float2(acc0[1]);
        float2 c10 = __half22float2(acc1[0]), c11 = __half22float2(acc1[1]);
        float2 c20 = __half22float2(acc2[0]), c21 = __half22float2(acc2[1]);
        float2 c30 = __half22float2(acc3[0]), c31 = __half22float2(acc3[1]);
        a.x += (c00.x + c10.x) + (c20.x + c30.x);
        a.y += (c00.y + c10.y) + (c20.y + c30.y);
        a.z += (c01.x + c11.x) + (c21.x + c31.x);
        a.w += (c01.y + c11.y) + (c21.y + c31.y);
    }

    float dw = g_dinv[w];
    float4 bb = *(const float4*)(b + coff);
    float4 p;
    p.x = fmaxf(a.x * dw + bb.x, 0.f);
    p.y = fmaxf(a.y * dw + bb.y, 0.f);
    p.z = fmaxf(a.z * dw + bb.z, 0.f);
    p.w = fmaxf(a.w * dw + bb.w, 0.f);

    int g = __ldg(batch + w);
    if (lane == 0) sg[wid] = g;
    __syncthreads();
    int g0 = sg[0];
    bool uni = true;
#pragma unroll
    for (int i = 1; i < 8; i++) uni &= (sg[i] == g0);

    if (uni) {
        *(float4*)&sacc[wid][lane * 4] = p;
        __syncthreads();
        if (wid == 0) {
            float4 s = make_float4(0.f, 0.f, 0.f, 0.f);
#pragma unroll
            for (int k = 0; k < 8; k++) {
                float4 v = *(const float4*)&sacc[k][lane * 4];
                s.x += v.x; s.y += v.y; s.z += v.z; s.w += v.w;
            }
            red4(g_pooled + (size_t)g0 * HH + coff, s);
        }
    } else {
        red4(g_pooled + (size_t)g * HH + coff, p);   // rare boundary blocks
    }
}

// -------------------------------------------------------------------------
// one block per group: mean -> fc1+relu -> actor softmax + critic
__global__ __launch_bounds__(128) void k_head2(const int* __restrict__ batch,
                                               const float* __restrict__ fc1_w,
                                               const float* __restrict__ fc1_b,
                                               const float* __restrict__ aw,
                                               const float* __restrict__ ab,
                                               const float* __restrict__ cw,
                                               const float* __restrict__ cb,
                                               float* __restrict__ out) {
    __shared__ float gs[HH];
    __shared__ float zp[2][HH2];
    __shared__ float zz[HH2];
    __shared__ float lg[TT];
    __shared__ int lbs[2];
    int g = blockIdx.x;
    int tid = threadIdx.x;

    if (tid < 2) {
        int target = g + tid, lo = 0, hi = NN;
        while (lo < hi) {
            int mid = (lo + hi) >> 1;
            if (__ldg(batch + mid) < target) lo = mid + 1; else hi = mid;
        }
        lbs[tid] = lo;
    }
    __syncthreads();

    float cnt = fmaxf((float)(lbs[1] - lbs[0]), 1.0f);
    gs[tid] = g_pooled[g * HH + tid] / cnt;
    __syncthreads();

    // z partials: 128 threads = 64 outputs x 2 K-halves
    {
        int j = tid & 63, h = tid >> 6;
        float s = 0.f;
        const float* wp = fc1_w + (size_t)(h * 64) * HH2 + j;
        const float* gp = gs + h * 64;
#pragma unroll 8
        for (int k = 0; k < 64; k++) s += gp[k] * wp[(size_t)k * HH2];
        zp[h][j] = s;
    }
    __syncthreads();
    if (tid < HH2) zz[tid] = fmaxf(zp[0][tid] + zp[1][tid] + fc1_b[tid], 0.f);
    __syncthreads();

    if (tid < TT) {
        float s = ab[tid];
#pragma unroll
        for (int k = 0; k < HH2; k++) s += zz[k] * aw[k * TT + tid];
        lg[tid] = s;
    }
    if (tid == 32) {   // separate warp: critic
        float s = cb[0];
#pragma unroll
        for (int k = 0; k < HH2; k++) s += zz[k] * cw[k];
        out[GG * TT + g] = s;
    }
    __syncthreads();

    if (tid == 0) {
        float m = -1e30f;
#pragma unroll
        for (int t = 0; t < TT; t++) m = fmaxf(m, lg[t]);
        float e[TT], sum = 0.f;
#pragma unroll
        for (int t = 0; t < TT; t++) { e[t] = expf(lg[t] - m); sum += e[t]; }
        float inv = 1.0f / sum;
#pragma unroll
        for (int t = 0; t < TT; t++) out[g * TT + t] = e[t] * inv;
    }
}

// -------------------------------------------------------------------------
extern "C" void kernel_launch(void* const* d_in, const int* in_sizes, int n_in,
                              void* d_out, int out_size) {
    const float* x     = (const float*)d_in[0];
    const int*   ei    = (const int*)d_in[1];
    const int*   batch = (const int*)d_in[2];
    const float* W     = (const float*)d_in[3];
    const float* b     = (const float*)d_in[4];
    const float* fc1_w = (const float*)d_in[5];
    const float* fc1_b = (const float*)d_in[6];
    const float* aw    = (const float*)d_in[7];
    const float* ab    = (const float*)d_in[8];
    const float* cw    = (const float*)d_in[9];
    const float* cb    = (const float*)d_in[10];
    float* out = (float*)d_out;

    void *p_cnt, *p_pooled;
    cudaGetSymbolAddress(&p_cnt,    g_cnt);
    cudaGetSymbolAddress(&p_pooled, g_pooled);

    cudaStream_t s2;
    cudaStreamCreateWithFlags(&s2, cudaStreamNonBlocking);
    cudaEvent_t eFork, eSide;
    cudaEventCreateWithFlags(&eFork, cudaEventDisableTiming);
    cudaEventCreateWithFlags(&eSide, cudaEventDisableTiming);

    // main stream: zero pooled, fork, GEMM (no dependencies on edge data)
    cudaMemsetAsync(p_pooled, 0, GG * HH * sizeof(float), 0);
    cudaEventRecord(eFork, 0);
    cudaStreamWaitEvent(s2, eFork, 0);

    // side stream: adjacency build + dinv
    cudaMemsetAsync(p_cnt, 0x00, NN * sizeof(int), s2);
    k_edges<<<(EE + 255) / 256, 256, 0, s2>>>(ei);
    k_dinv<<<(NN + 255) / 256, 256, 0, s2>>>();
    cudaEventRecord(eSide, s2);

    k_gemm<<<(NN + GM - 1) / GM, 256>>>(x, W);

    // join: scale needs hs (main) + dinv (side); then gather, head
    cudaStreamWaitEvent(0, eSide, 0);
    k_scale<<<(NN * 16 + 255) / 256, 256>>>();
    k_gather<<<NN / 8, 256>>>(batch, b);
    k_head2<<<GG, 128>>>(batch, fc1_w, fc1_b, aw, ab, cw, cb, out);
}